// round 17
// baseline (speedup 1.0000x reference)
#include <cuda_runtime.h>
#include <cstdint>

// ---------------------------------------------------------------------------
// GNBlock: h = BN(PReLU(segment_sum(relu(x[src]@W1+b1)@W2+b2, dst) + x@W_root + b_root))
// N=50000, E=800000, C_IN=64, C_HID=128, C_OUT=64
//
// R16 base (98.8us) with k-parity-packed FMA2: accumulators hold
// (sum_even_k, sum_odd_k) per output column, so x/h operands are contiguous
// float2 -> direct LDS.64 (no pack MOVs); weights staged k-interleaved.
// GEMM1+3 fused, two 4-row passes (bounded registers); GEMM2 k-parity too.
// Scatter / epilogue identical to R16.
// ---------------------------------------------------------------------------

#define N_MAX 50000
#define C_IN 64
#define C_HID 128
#define C_OUT 64
#define TILE_N 128
#define MT 512
#define NT 256

__device__ __align__(16) float g_h[N_MAX * C_OUT];    // root transform (pre-PReLU)
__device__ __align__(16) float g_msg[N_MAX * C_OUT];  // per-node messages
__device__ float g_stats[2 * C_OUT];
__device__ int g_idx64;

typedef unsigned long long u64;

// ---- f32x2 packed helpers ---------------------------------------------------
__device__ __forceinline__ u64 pack_lohi(float lo, float hi) {
    u64 r;
    asm("mov.b64 %0, {%1, %2};"
        : "=l"(r) : "r"(__float_as_uint(lo)), "r"(__float_as_uint(hi)));
    return r;
}
__device__ __forceinline__ u64 fma2(u64 a, u64 b, u64 c) {
    u64 d;
    asm("fma.rn.f32x2 %0, %1, %2, %3;" : "=l"(d) : "l"(a), "l"(b), "l"(c));
    return d;
}
__device__ __forceinline__ float hsum2(u64 v) {
    unsigned int lo, hi;
    asm("mov.b64 {%0, %1}, %2;" : "=r"(lo), "=r"(hi) : "l"(v));
    return __uint_as_float(lo) + __uint_as_float(hi);
}

// ---------------------------------------------------------------------------
// K1: PERSISTENT fused per-node kernel (double-buffered X):
//   fused GEMM1+GEMM3, k-parity packed, 2 passes of 4 rows:
//     sH = relu(sX@W1+b1) ; g_h = sX@Wr+br
//   GEMM2 k-parity packed (4 rows x 4 cols): g_msg = sH@W2+b2
// smem: W1p 32KB | W2p 32KB | Wrp 16KB | 2x X(128x68) 68KB | sH(128x132) 66KB
// ---------------------------------------------------------------------------
#define SX_PITCH 68
#define SH_PITCH 132
#define XBUF (TILE_N * SX_PITCH)
#define SMEM_FLOATS (8192 + 8192 + 4096 + 2 * XBUF + TILE_N * SH_PITCH + 256)
#define SMEM_BYTES (SMEM_FLOATS * 4)

__global__ __launch_bounds__(MT) void msg_kernel(
    const float* __restrict__ x, const float* __restrict__ W1,
    const float* __restrict__ b1, const float* __restrict__ W2,
    const float* __restrict__ b2, const float* __restrict__ Wr,
    const float* __restrict__ br, const void* __restrict__ ei, int N,
    int numTiles) {
    extern __shared__ float sm[];
    u64* sW1p = reinterpret_cast<u64*>(sm);      // [k2=32][c=128] (32KB)
    u64* sW2p = sW1p + 4096;                     // [j2=64][c=64]  (32KB)
    u64* sWrp = sW2p + 4096;                     // [k2=32][c=64]  (16KB)
    float* sX0 = reinterpret_cast<float*>(sWrp + 2048);  // 2 x (128 x 68)
    float* sH = sX0 + 2 * XBUF;                  // 128 x 132
    float* sb1 = sH + TILE_N * SH_PITCH;         // 128
    float* sb2 = sb1 + 128;                      // 64
    float* sbr = sb2 + 64;                       // 64

    const int tid = threadIdx.x;

    // folded setup (block 0): zero stats + dtype probe
    if (blockIdx.x == 0) {
        if (tid < 128) g_stats[tid] = 0.f;
        if (tid >= 128 && tid < 160) {
            const long long* p = (const long long*)ei;
            long long v = p[tid - 128];
            unsigned ok = __ballot_sync(0xffffffffu, v >= 0 && v < (long long)N);
            if (tid == 128) g_idx64 = (ok == 0xffffffffu) ? 1 : 0;
        }
    }

    // stage weights k-interleaved: sW1p[k2*128+c] = (W1[2k2][c], W1[2k2+1][c])
    for (int i = tid; i < 4096; i += MT) {
        int k2 = i >> 7, c = i & 127;
        sW1p[i] = pack_lohi(W1[(2 * k2) * C_HID + c], W1[(2 * k2 + 1) * C_HID + c]);
    }
    for (int i = tid; i < 4096; i += MT) {
        int j2 = i >> 6, c = i & 63;
        sW2p[i] = pack_lohi(W2[(2 * j2) * C_OUT + c], W2[(2 * j2 + 1) * C_OUT + c]);
    }
    for (int i = tid; i < 2048; i += MT) {
        int k2 = i >> 6, c = i & 63;
        sWrp[i] = pack_lohi(Wr[(2 * k2) * C_OUT + c], Wr[(2 * k2 + 1) * C_OUT + c]);
    }
    if (tid < 128) sb1[tid] = b1[tid];
    else if (tid < 192) sb2[tid - 128] = b2[tid - 128];
    else if (tid < 256) sbr[tid - 192] = br[tid - 192];

    // fused GEMM1+3 mapping: lane -> cols (broadcast X within warp); warp -> 8 rows
    const int lane = tid & 31;
    const int wrp = tid >> 5;     // 0..15
    const int hb = lane * 4;      // GEMM1 cols
    const int cb = lane * 2;      // GEMM3 cols
    // GEMM2 mapping: 4 rows x 4 cols
    const int hg2 = tid & 15;
    const int rg2 = tid >> 4;
    const int kb2 = hg2 * 4;
    const int rb2 = rg2 * 4;

    int tile = blockIdx.x;
    int bufIdx = 0;

    // stage first tile
    if (tile < numTiles) {
#pragma unroll
        for (int j = 0; j < 4; j++) {
            int i = j * MT + tid;
            int r = i >> 4, q = i & 15;
            int n = tile * TILE_N + r;
            if (n >= N) n = N - 1;
            float4 v = reinterpret_cast<const float4*>(x + (long long)n * C_IN)[q];
            *reinterpret_cast<float4*>(&sX0[r * SX_PITCH + q * 4]) = v;
        }
    }
    __syncthreads();

    for (; tile < numTiles; tile += gridDim.x, bufIdx ^= 1) {
        const int n0 = tile * TILE_N;
        float* sXc = sX0 + bufIdx * XBUF;
        float* sXn = sX0 + (bufIdx ^ 1) * XBUF;
        const int next = tile + gridDim.x;

        // prefetch next tile's X (hidden behind GEMM1+3)
        float4 pf[4];
        if (next < numTiles) {
#pragma unroll
            for (int j = 0; j < 4; j++) {
                int i = j * MT + tid;
                int r = i >> 4, q = i & 15;
                int n = next * TILE_N + r;
                if (n >= N) n = N - 1;
                pf[j] = __ldg(&reinterpret_cast<const float4*>(x + (long long)n * C_IN)[q]);
            }
        }

        // ---- fused GEMM1 + GEMM3, k-parity packed, two 4-row passes ----
#pragma unroll
        for (int pass = 0; pass < 2; pass++) {
            const int rbase = wrp * 8 + pass * 4;
            u64 a1[4][4];
            u64 a3[4][2];
#pragma unroll
            for (int e = 0; e < 4; e++) {
                a1[e][0] = a1[e][1] = a1[e][2] = a1[e][3] = 0ULL;
                a3[e][0] = a3[e][1] = 0ULL;
            }

#pragma unroll 4
            for (int k2 = 0; k2 < C_IN / 2; k2++) {
                ulonglong2 w1a = *reinterpret_cast<const ulonglong2*>(&sW1p[k2 * 128 + hb]);
                ulonglong2 w1b =
                    *reinterpret_cast<const ulonglong2*>(&sW1p[k2 * 128 + hb + 2]);
                ulonglong2 w3 = *reinterpret_cast<const ulonglong2*>(&sWrp[k2 * 64 + cb]);
#pragma unroll
                for (int e = 0; e < 4; e++) {
                    u64 xp = *reinterpret_cast<const u64*>(&sXc[(rbase + e) * SX_PITCH + 2 * k2]);
                    a1[e][0] = fma2(xp, w1a.x, a1[e][0]);
                    a1[e][1] = fma2(xp, w1a.y, a1[e][1]);
                    a1[e][2] = fma2(xp, w1b.x, a1[e][2]);
                    a1[e][3] = fma2(xp, w1b.y, a1[e][3]);
                    a3[e][0] = fma2(xp, w3.x, a3[e][0]);
                    a3[e][1] = fma2(xp, w3.y, a3[e][1]);
                }
            }

            // GEMM1 epilogue: horizontal sum + bias + relu -> sH
            float bb0 = sb1[hb], bb1 = sb1[hb + 1], bb2 = sb1[hb + 2], bb3 = sb1[hb + 3];
#pragma unroll
            for (int e = 0; e < 4; e++) {
                float4 r;
                r.x = fmaxf(hsum2(a1[e][0]) + bb0, 0.f);
                r.y = fmaxf(hsum2(a1[e][1]) + bb1, 0.f);
                r.z = fmaxf(hsum2(a1[e][2]) + bb2, 0.f);
                r.w = fmaxf(hsum2(a1[e][3]) + bb3, 0.f);
                *reinterpret_cast<float4*>(&sH[(rbase + e) * SH_PITCH + hb]) = r;
            }
            // GEMM3 epilogue: horizontal sum + bias -> g_h
            float c0 = sbr[cb], c1 = sbr[cb + 1];
#pragma unroll
            for (int e = 0; e < 4; e++) {
                int n = n0 + rbase + e;
                if (n >= N) continue;
                float2 r;
                r.x = hsum2(a3[e][0]) + c0;
                r.y = hsum2(a3[e][1]) + c1;
                *reinterpret_cast<float2*>(&g_h[(long long)n * C_OUT + cb]) = r;
            }
        }

        // store prefetched X into the other buffer
        if (next < numTiles) {
#pragma unroll
            for (int j = 0; j < 4; j++) {
                int i = j * MT + tid;
                int r = i >> 4, q = i & 15;
                *reinterpret_cast<float4*>(&sXn[r * SX_PITCH + q * 4]) = pf[j];
            }
        }
        __syncthreads();  // sH complete; next-X staged

        // ---- GEMM2: g_msg = sH @ W2 + b2, k-parity packed ----
        {
            u64 a2[4][4];
#pragma unroll
            for (int e = 0; e < 4; e++)
                a2[e][0] = a2[e][1] = a2[e][2] = a2[e][3] = 0ULL;

#pragma unroll 4
            for (int j2 = 0; j2 < C_HID / 2; j2++) {
                ulonglong2 wa = *reinterpret_cast<const ulonglong2*>(&sW2p[j2 * 64 + kb2]);
                ulonglong2 wb =
                    *reinterpret_cast<const ulonglong2*>(&sW2p[j2 * 64 + kb2 + 2]);
#pragma unroll
                for (int e = 0; e < 4; e++) {
                    u64 hp = *reinterpret_cast<const u64*>(&sH[(rb2 + e) * SH_PITCH + 2 * j2]);
                    a2[e][0] = fma2(hp, wa.x, a2[e][0]);
                    a2[e][1] = fma2(hp, wa.y, a2[e][1]);
                    a2[e][2] = fma2(hp, wb.x, a2[e][2]);
                    a2[e][3] = fma2(hp, wb.y, a2[e][3]);
                }
            }
            float c0 = sb2[kb2], c1 = sb2[kb2 + 1], c2 = sb2[kb2 + 2], c3 = sb2[kb2 + 3];
#pragma unroll
            for (int e = 0; e < 4; e++) {
                int n = n0 + rb2 + e;
                if (n >= N) continue;
                float4 r;
                r.x = hsum2(a2[e][0]) + c0;
                r.y = hsum2(a2[e][1]) + c1;
                r.z = hsum2(a2[e][2]) + c2;
                r.w = hsum2(a2[e][3]) + c3;
                *reinterpret_cast<float4*>(&g_msg[(long long)n * C_OUT + kb2]) = r;
            }
        }
        __syncthreads();  // GEMM2's sH reads done before next GEMM1 writes sH
    }
}

// ---------------------------------------------------------------------------
// K2: scatter  g_h[dst] += g_msg[src].  16 threads per edge-slot; each slot
// handles 4 edges at stride G -> 4 independent idx->msg->RED chains (MLP=4).
// ---------------------------------------------------------------------------
__global__ __launch_bounds__(NT) void scatter_kernel(const void* __restrict__ ei_raw,
                                                     int E, int G) {
    long long idx = (long long)blockIdx.x * NT + threadIdx.x;
    int base = (int)(idx >> 4);
    int q = (int)(idx & 15);
    if (base >= G) return;

    const int idx64 = g_idx64;
    int e0 = base, e1 = base + G, e2 = base + 2 * G, e3 = base + 3 * G;
    bool v0 = e0 < E, v1 = e1 < E, v2 = e2 < E, v3 = e3 < E;

    int s0 = 0, d0 = 0, s1 = 0, d1 = 0, s2 = 0, d2 = 0, s3 = 0, d3 = 0;
    if (idx64) {
        const long long* p = (const long long*)ei_raw;
        if (v0) { s0 = (int)__ldg(&p[e0]); d0 = (int)__ldg(&p[E + e0]); }
        if (v1) { s1 = (int)__ldg(&p[e1]); d1 = (int)__ldg(&p[E + e1]); }
        if (v2) { s2 = (int)__ldg(&p[e2]); d2 = (int)__ldg(&p[E + e2]); }
        if (v3) { s3 = (int)__ldg(&p[e3]); d3 = (int)__ldg(&p[E + e3]); }
    } else {
        const int* p = (const int*)ei_raw;
        if (v0) { s0 = __ldg(&p[e0]); d0 = __ldg(&p[E + e0]); }
        if (v1) { s1 = __ldg(&p[e1]); d1 = __ldg(&p[E + e1]); }
        if (v2) { s2 = __ldg(&p[e2]); d2 = __ldg(&p[E + e2]); }
        if (v3) { s3 = __ldg(&p[e3]); d3 = __ldg(&p[E + e3]); }
    }

    float4 m0, m1, m2, m3;
    if (v0) m0 = *reinterpret_cast<const float4*>(&g_msg[(long long)s0 * C_OUT + q * 4]);
    if (v1) m1 = *reinterpret_cast<const float4*>(&g_msg[(long long)s1 * C_OUT + q * 4]);
    if (v2) m2 = *reinterpret_cast<const float4*>(&g_msg[(long long)s2 * C_OUT + q * 4]);
    if (v3) m3 = *reinterpret_cast<const float4*>(&g_msg[(long long)s3 * C_OUT + q * 4]);

    if (v0) {
        float* pd = &g_h[(long long)d0 * C_OUT + q * 4];
        asm volatile("red.global.add.v4.f32 [%0], {%1,%2,%3,%4};"
                     :: "l"(pd), "f"(m0.x), "f"(m0.y), "f"(m0.z), "f"(m0.w) : "memory");
    }
    if (v1) {
        float* pd = &g_h[(long long)d1 * C_OUT + q * 4];
        asm volatile("red.global.add.v4.f32 [%0], {%1,%2,%3,%4};"
                     :: "l"(pd), "f"(m1.x), "f"(m1.y), "f"(m1.z), "f"(m1.w) : "memory");
    }
    if (v2) {
        float* pd = &g_h[(long long)d2 * C_OUT + q * 4];
        asm volatile("red.global.add.v4.f32 [%0], {%1,%2,%3,%4};"
                     :: "l"(pd), "f"(m2.x), "f"(m2.y), "f"(m2.z), "f"(m2.w) : "memory");
    }
    if (v3) {
        float* pd = &g_h[(long long)d3 * C_OUT + q * 4];
        asm volatile("red.global.add.v4.f32 [%0], {%1,%2,%3,%4};"
                     :: "l"(pd), "f"(m3.x), "f"(m3.y), "f"(m3.z), "f"(m3.w) : "memory");
    }
}

// ---------------------------------------------------------------------------
// K3: READ-ONLY stats pass: per-channel sum/sumsq of PReLU(g_h).
// ---------------------------------------------------------------------------
__global__ void prelu_stats_kernel(const float* __restrict__ prelu_w, int N) {
    const float a = prelu_w[0];
    const int total4 = N * (C_OUT / 4);
    const int stride = gridDim.x * blockDim.x;
    const float4* gh4 = reinterpret_cast<const float4*>(g_h);
    float s0 = 0.f, s1 = 0.f, s2 = 0.f, s3 = 0.f;
    float q0 = 0.f, q1 = 0.f, q2 = 0.f, q3 = 0.f;
    for (int i = blockIdx.x * blockDim.x + threadIdx.x; i < total4; i += stride) {
        float4 v = gh4[i];
        v.x = (v.x >= 0.f) ? v.x : a * v.x;
        v.y = (v.y >= 0.f) ? v.y : a * v.y;
        v.z = (v.z >= 0.f) ? v.z : a * v.z;
        v.w = (v.w >= 0.f) ? v.w : a * v.w;
        s0 += v.x; s1 += v.y; s2 += v.z; s3 += v.w;
        q0 += v.x * v.x; q1 += v.y * v.y; q2 += v.z * v.z; q3 += v.w * v.w;
    }
    __shared__ float rs[NT * 4], rq[NT * 4];
    int t = threadIdx.x;
    rs[t * 4 + 0] = s0; rs[t * 4 + 1] = s1; rs[t * 4 + 2] = s2; rs[t * 4 + 3] = s3;
    rq[t * 4 + 0] = q0; rq[t * 4 + 1] = q1; rq[t * 4 + 2] = q2; rq[t * 4 + 3] = q3;
    __syncthreads();
    if (t < 64) {
        int qq = t >> 2, comp = t & 3;
        float ts = 0.f, tq = 0.f;
#pragma unroll
        for (int m = 0; m < 16; m++) {
            int src = (m * 16 + qq) * 4 + comp;
            ts += rs[src];
            tq += rq[src];
        }
        atomicAdd(&g_stats[t], ts);
        atomicAdd(&g_stats[64 + t], tq);
    }
}

// ---------------------------------------------------------------------------
// K4: finalize — recompute PReLU, normalize, write out
// ---------------------------------------------------------------------------
__global__ void bn_kernel(float* __restrict__ out, const float* __restrict__ gamma,
                          const float* __restrict__ beta,
                          const float* __restrict__ prelu_w, int N) {
    __shared__ float sscale[C_OUT], sshift[C_OUT];
    if (threadIdx.x < C_OUT) {
        float invN = 1.f / (float)N;
        float mu = g_stats[threadIdx.x] * invN;
        float var = g_stats[64 + threadIdx.x] * invN - mu * mu;
        float inv = rsqrtf(var + 1e-5f);
        float g = gamma[threadIdx.x] * inv;
        sscale[threadIdx.x] = g;
        sshift[threadIdx.x] = beta[threadIdx.x] - mu * g;
    }
    __syncthreads();
    const float a = prelu_w[0];
    const int total4 = N * (C_OUT / 4);
    const int stride = gridDim.x * blockDim.x;
    const float4* gh4 = reinterpret_cast<const float4*>(g_h);
    float4* o4 = reinterpret_cast<float4*>(out);
    for (int i = blockIdx.x * blockDim.x + threadIdx.x; i < total4; i += stride) {
        int q = (i & 15);
        float4 sc = reinterpret_cast<const float4*>(sscale)[q];
        float4 sh = reinterpret_cast<const float4*>(sshift)[q];
        float4 v = gh4[i];
        v.x = (v.x >= 0.f) ? v.x : a * v.x;
        v.y = (v.y >= 0.f) ? v.y : a * v.y;
        v.z = (v.z >= 0.f) ? v.z : a * v.z;
        v.w = (v.w >= 0.f) ? v.w : a * v.w;
        float4 r;
        r.x = fmaf(v.x, sc.x, sh.x);
        r.y = fmaf(v.y, sc.y, sh.y);
        r.z = fmaf(v.z, sc.z, sh.z);
        r.w = fmaf(v.w, sc.w, sh.w);
        o4[i] = r;
    }
}

// ---------------------------------------------------------------------------
extern "C" void kernel_launch(void* const* d_in, const int* in_sizes, int n_in,
                              void* d_out, int out_size) {
    const float* x = (const float*)d_in[0];
    const void* ei = d_in[1];
    const float* W1 = (const float*)d_in[2];
    const float* b1 = (const float*)d_in[3];
    const float* W2 = (const float*)d_in[4];
    const float* b2 = (const float*)d_in[5];
    const float* Wr = (const float*)d_in[6];
    const float* br = (const float*)d_in[7];
    const float* pw = (const float*)d_in[8];
    const float* gamma = (const float*)d_in[9];
    const float* beta = (const float*)d_in[10];
    float* out = (float*)d_out;

    const int N = in_sizes[0] / C_IN;
    const int E = in_sizes[1] / 2;
    const int numTiles = (N + TILE_N - 1) / TILE_N;
    const int G = (E + 3) / 4;

    static int nSM = 0;
    if (nSM == 0) cudaDeviceGetAttribute(&nSM, cudaDevAttrMultiProcessorCount, 0);

    cudaFuncSetAttribute(msg_kernel, cudaFuncAttributeMaxDynamicSharedMemorySize,
                         SMEM_BYTES);

    // K1: persistent per-node MLP + root transform (setup folded into block 0)
    msg_kernel<<<nSM, MT, SMEM_BYTES>>>(x, W1, b1, W2, b2, Wr, br, ei, N, numTiles);

    // K2: edge scatter, 4 edges per 16-thread slot
    const long long units = (long long)G * 16;
    scatter_kernel<<<(int)((units + NT - 1) / NT), NT>>>(ei, E, G);

    // K3: stats (read-only)
    prelu_stats_kernel<<<592, NT>>>(pw, N);

    // K4: PReLU + BN normalize -> out
    bn_kernel<<<592, NT>>>(out, gamma, beta, pw, N);
}